// round 3
// baseline (speedup 1.0000x reference)
#include <cuda_runtime.h>
#include <math.h>

// ---------------------------------------------------------------------------
// Scratch (device globals; no allocation in kernel_launch)
// ---------------------------------------------------------------------------
__device__ float g_feat1[2 * 512 * 4096];
__device__ float g_feat2[2 * 512 * 4096];
__device__ float g_q[2 * 64 * 4096];
__device__ float g_k[2 * 64 * 4096];
__device__ float g_v[2 * 512 * 4096];
__device__ float g_energy[2 * 4096 * 4096];     // 134 MB PAM attention logits
__device__ float g_sa_feat[2 * 512 * 4096];
__device__ float g_sc_feat[2 * 512 * 4096];
__device__ float g_sa_conv[2 * 512 * 4096];
__device__ float g_cam_e[2 * 512 * 512];
__device__ float g_scale[4 * 512];
__device__ float g_bias[4 * 512];

// ---------------------------------------------------------------------------
// Fold BN (inference) into per-channel scale/bias: y = x*inv + (b - m*inv)
// sets: 0=bn5a, 1=bn5c, 2=bn51, 3=bn52
// ---------------------------------------------------------------------------
__global__ void fold_bn_kernel(
    const float* s0, const float* b0, const float* m0, const float* v0,
    const float* s1, const float* b1, const float* m1, const float* v1,
    const float* s2, const float* b2, const float* m2, const float* v2,
    const float* s3, const float* b3, const float* m3, const float* v3)
{
    const float* S[4] = {s0, s1, s2, s3};
    const float* B[4] = {b0, b1, b2, b3};
    const float* M[4] = {m0, m1, m2, m3};
    const float* V[4] = {v0, v1, v2, v3};
    int set = blockIdx.x;
    int c = threadIdx.x;  // 0..511
    float inv = rsqrtf(V[set][c] + 1e-5f) * S[set][c];
    g_scale[set * 512 + c] = inv;
    g_bias[set * 512 + c]  = B[set][c] - M[set][c] * inv;
}

// ---------------------------------------------------------------------------
// 3x3 conv (pad 1) + folded BN + ReLU (+ optional post-ReLU addend), Cout=512.
// Block computes [64 co] x [one image row of 64 px]. 128 threads,
// per-thread 8co x 4px register tile. K-chunk = 8 input channels (72 MACs).
// Grid: (Cout/64, 64 rows, B)
// ---------------------------------------------------------------------------
__global__ __launch_bounds__(128) void conv3x3_bn_relu(
    const float* __restrict__ x, const float* __restrict__ w,
    int Cin, int bnset,
    const float* __restrict__ addend, float* __restrict__ out)
{
    __shared__ float ws[72][64];       // [k = ci_local*9 + dy*3 + dx][co_local]
    __shared__ float xs[8][3][68];     // [ci_local][row dy][col (gx = c-1)]

    const int coBase = blockIdx.x * 64;
    const int y      = blockIdx.y;
    const int bb     = blockIdx.z;
    const int tid    = threadIdx.x;
    const int tc     = tid >> 4;       // 0..7  -> co group of 8
    const int tn     = tid & 15;       // 0..15 -> px group of 4
    const int co0l   = tc * 8;
    const int px0    = tn * 4;

    float acc[8][4];
#pragma unroll
    for (int i = 0; i < 8; i++)
#pragma unroll
        for (int j = 0; j < 4; j++) acc[i][j] = 0.f;

    const float* xb = x + (size_t)bb * Cin * 4096;

    // weight-load assignment: 2 threads per co_local, 36 contiguous floats each
    const int co_l = tid >> 1;
    const int half = tid & 1;
    const float* wrow = w + (size_t)(coBase + co_l) * Cin * 9;

    for (int ciB = 0; ciB < Cin; ciB += 8) {
        // ---- load weights: 8 ci x 9 taps, contiguous in global per co ----
        {
            const float* wp = wrow + (size_t)ciB * 9 + half * 36;
#pragma unroll
            for (int j = 0; j < 36; j++) ws[half * 36 + j][co_l] = wp[j];
        }
        // ---- load input tile: 8 ci x 3 rows x 66 cols (zero-padded) ----
        for (int e = tid; e < 8 * 3 * 66; e += 128) {
            int ci = e / 198;
            int r  = (e / 66) % 3;
            int c  = e % 66;
            int gy = y - 1 + r;
            int gx = c - 1;
            float v = 0.f;
            if ((unsigned)gy < 64u && (unsigned)gx < 64u)
                v = xb[((ciB + ci) * 64 + gy) * 64 + gx];
            xs[ci][r][c] = v;
        }
        __syncthreads();

        for (int kc = 0; kc < 8; kc++) {
#pragma unroll
            for (int dy = 0; dy < 3; dy++) {
                float xf[6];
#pragma unroll
                for (int i = 0; i < 6; i++) xf[i] = xs[kc][dy][px0 + i];
#pragma unroll
                for (int dx = 0; dx < 3; dx++) {
                    const int kk = kc * 9 + dy * 3 + dx;
                    const float4 w0 = *(const float4*)&ws[kk][co0l];
                    const float4 w1 = *(const float4*)&ws[kk][co0l + 4];
                    float wv8[8] = {w0.x, w0.y, w0.z, w0.w, w1.x, w1.y, w1.z, w1.w};
#pragma unroll
                    for (int i = 0; i < 8; i++)
#pragma unroll
                        for (int j = 0; j < 4; j++)
                            acc[i][j] += wv8[i] * xf[dx + j];
                }
            }
        }
        __syncthreads();
    }

    // ---- epilogue: BN + ReLU (+ addend) ----
#pragma unroll
    for (int i = 0; i < 8; i++) {
        const int co = coBase + co0l + i;
        const float s  = g_scale[bnset * 512 + co];
        const float bi = g_bias[bnset * 512 + co];
        const size_t base = (((size_t)bb * 512 + co) * 64 + y) * 64;
#pragma unroll
        for (int j = 0; j < 4; j++) {
            float v = fmaxf(acc[i][j] * s + bi, 0.f);
            if (addend) v += addend[base + px0 + j];
            out[base + px0 + j] = v;
        }
    }
}

// ---------------------------------------------------------------------------
// Tiled SGEMM: C[m][n] = sum_k a(m,k)*b(k,n), 64x64 tile, BK=16, 128 threads.
//   AM==0:     a(m,k) = A[m*lda + k]      AM==1: a(m,k) = A[k*lda + m]
//   BMODE==1:  b(k,n) = B[k*ldb + n]   BMODE==0: b(k,n) = B[n*ldb + k]
// EP: 0 = none, 1 = +bias[m], 2 = gamma[0]*acc + add[b*sAdd + m*N + n]
// All M,N multiples of 64; K multiple of 16. ldc == N. Grid (M/64, N/64, B).
// ---------------------------------------------------------------------------
template <int AM, int BMODE, int EP>
__global__ __launch_bounds__(128) void gemm_kernel(
    const float* __restrict__ A, const float* __restrict__ Bm,
    float* __restrict__ C, int N, int K, int lda, int ldb,
    long sA, long sB, long sC,
    const float* __restrict__ bias, const float* __restrict__ gamma,
    const float* __restrict__ add, long sAdd)
{
    const int b = blockIdx.z;
    A  += (size_t)b * sA;
    Bm += (size_t)b * sB;
    C  += (size_t)b * sC;

    const int mBase = blockIdx.x * 64;
    const int nBase = blockIdx.y * 64;

    __shared__ float As[16][68];
    __shared__ float Bs[16][68];

    float acc[8][4];
#pragma unroll
    for (int i = 0; i < 8; i++)
#pragma unroll
        for (int j = 0; j < 4; j++) acc[i][j] = 0.f;

    const int tid = threadIdx.x;
    const int tc = tid >> 4;   // 0..7
    const int tn = tid & 15;   // 0..15

    for (int kb = 0; kb < K; kb += 16) {
        // ---- stage A tile -> As[k][m] ----
        if (AM == 0) {
            const int m  = tid >> 1;
            const int ko = (tid & 1) * 8;
            const float* p = A + (size_t)(mBase + m) * lda + kb + ko;
            float4 v0 = *(const float4*)p;
            float4 v1 = *(const float4*)(p + 4);
            As[ko + 0][m] = v0.x; As[ko + 1][m] = v0.y;
            As[ko + 2][m] = v0.z; As[ko + 3][m] = v0.w;
            As[ko + 4][m] = v1.x; As[ko + 5][m] = v1.y;
            As[ko + 6][m] = v1.z; As[ko + 7][m] = v1.w;
        } else {
            const int k  = tid >> 3;
            const int mo = (tid & 7) * 8;
            const float* p = A + (size_t)(kb + k) * lda + mBase + mo;
            *(float4*)&As[k][mo]     = *(const float4*)p;
            *(float4*)&As[k][mo + 4] = *(const float4*)(p + 4);
        }
        // ---- stage B tile -> Bs[k][n] ----
        if (BMODE == 0) {
            const int n  = tid >> 1;
            const int ko = (tid & 1) * 8;
            const float* p = Bm + (size_t)(nBase + n) * ldb + kb + ko;
            float4 v0 = *(const float4*)p;
            float4 v1 = *(const float4*)(p + 4);
            Bs[ko + 0][n] = v0.x; Bs[ko + 1][n] = v0.y;
            Bs[ko + 2][n] = v0.z; Bs[ko + 3][n] = v0.w;
            Bs[ko + 4][n] = v1.x; Bs[ko + 5][n] = v1.y;
            Bs[ko + 6][n] = v1.z; Bs[ko + 7][n] = v1.w;
        } else {
            const int k  = tid >> 3;
            const int no = (tid & 7) * 8;
            const float* p = Bm + (size_t)(kb + k) * ldb + nBase + no;
            *(float4*)&Bs[k][no]     = *(const float4*)p;
            *(float4*)&Bs[k][no + 4] = *(const float4*)(p + 4);
        }
        __syncthreads();

#pragma unroll
        for (int k = 0; k < 16; k++) {
            float4 a0 = *(const float4*)&As[k][tc * 8];
            float4 a1 = *(const float4*)&As[k][tc * 8 + 4];
            float4 bf = *(const float4*)&Bs[k][tn * 4];
            float av[8] = {a0.x, a0.y, a0.z, a0.w, a1.x, a1.y, a1.z, a1.w};
            float bv[4] = {bf.x, bf.y, bf.z, bf.w};
#pragma unroll
            for (int i = 0; i < 8; i++)
#pragma unroll
                for (int j = 0; j < 4; j++)
                    acc[i][j] += av[i] * bv[j];
        }
        __syncthreads();
    }

    const int n0 = nBase + tn * 4;
#pragma unroll
    for (int i = 0; i < 8; i++) {
        const int m = mBase + tc * 8 + i;
        const size_t row = (size_t)m * N;
#pragma unroll
        for (int j = 0; j < 4; j++) {
            float v = acc[i][j];
            if (EP == 1) v += bias[m];
            if (EP == 2) v = gamma[0] * v + add[(size_t)b * sAdd + row + n0 + j];
            C[row + n0 + j] = v;
        }
    }
}

// ---------------------------------------------------------------------------
// Row softmax, row length 4096, in place. One block (256 thr) per row.
// 16 elements per thread held in registers -> 1 read + 1 write per element.
// ---------------------------------------------------------------------------
__global__ void softmax4096_kernel(float* __restrict__ e)
{
    float* p = e + (size_t)blockIdx.x * 4096;
    const int tid = threadIdx.x;

    float4 v[4];
    float mx = -1e30f;
#pragma unroll
    for (int i = 0; i < 4; i++) {
        v[i] = *(const float4*)&p[i * 1024 + tid * 4];
        mx = fmaxf(mx, fmaxf(fmaxf(v[i].x, v[i].y), fmaxf(v[i].z, v[i].w)));
    }
    // block max
    __shared__ float red[8];
#pragma unroll
    for (int off = 16; off; off >>= 1) mx = fmaxf(mx, __shfl_xor_sync(0xffffffffu, mx, off));
    if ((tid & 31) == 0) red[tid >> 5] = mx;
    __syncthreads();
    mx = red[0];
#pragma unroll
    for (int i = 1; i < 8; i++) mx = fmaxf(mx, red[i]);
    __syncthreads();

    float s = 0.f;
#pragma unroll
    for (int i = 0; i < 4; i++) {
        v[i].x = __expf(v[i].x - mx); v[i].y = __expf(v[i].y - mx);
        v[i].z = __expf(v[i].z - mx); v[i].w = __expf(v[i].w - mx);
        s += v[i].x + v[i].y + v[i].z + v[i].w;
    }
#pragma unroll
    for (int off = 16; off; off >>= 1) s += __shfl_xor_sync(0xffffffffu, s, off);
    if ((tid & 31) == 0) red[tid >> 5] = s;
    __syncthreads();
    s = 0.f;
#pragma unroll
    for (int i = 0; i < 8; i++) s += red[i];
    const float inv = 1.f / s;
#pragma unroll
    for (int i = 0; i < 4; i++) {
        v[i].x *= inv; v[i].y *= inv; v[i].z *= inv; v[i].w *= inv;
        *(float4*)&p[i * 1024 + tid * 4] = v[i];
    }
}

// ---------------------------------------------------------------------------
// CAM softmax over rows of 512: attn = softmax(rowmax - e) == exp(rowmin - e)/sum
// One block (128 thr) per row, in place.
// ---------------------------------------------------------------------------
__global__ void softmax512_cam_kernel(float* __restrict__ e)
{
    float* p = e + (size_t)blockIdx.x * 512;
    const int tid = threadIdx.x;

    float4 v = *(const float4*)&p[tid * 4];
    float mn = fminf(fminf(v.x, v.y), fminf(v.z, v.w));
    __shared__ float red[4];
#pragma unroll
    for (int off = 16; off; off >>= 1) mn = fminf(mn, __shfl_xor_sync(0xffffffffu, mn, off));
    if ((tid & 31) == 0) red[tid >> 5] = mn;
    __syncthreads();
    mn = fminf(fminf(red[0], red[1]), fminf(red[2], red[3]));
    __syncthreads();

    v.x = __expf(mn - v.x); v.y = __expf(mn - v.y);
    v.z = __expf(mn - v.z); v.w = __expf(mn - v.w);
    float s = v.x + v.y + v.z + v.w;
#pragma unroll
    for (int off = 16; off; off >>= 1) s += __shfl_xor_sync(0xffffffffu, s, off);
    if ((tid & 31) == 0) red[tid >> 5] = s;
    __syncthreads();
    s = red[0] + red[1] + red[2] + red[3];
    const float inv = 1.f / s;
    v.x *= inv; v.y *= inv; v.z *= inv; v.w *= inv;
    *(float4*)&p[tid * 4] = v;
}

// ---------------------------------------------------------------------------
// Launch
// ---------------------------------------------------------------------------
extern "C" void kernel_launch(void* const* d_in, const int* in_sizes, int n_in,
                              void* d_out, int out_size)
{
    (void)in_sizes; (void)n_in; (void)out_size;

    const float* x         = (const float*)d_in[0];
    const float* w5a       = (const float*)d_in[1];
    const float* w5c       = (const float*)d_in[6];
    const float* wq        = (const float*)d_in[11];
    const float* bq        = (const float*)d_in[12];
    const float* wk        = (const float*)d_in[13];
    const float* bk        = (const float*)d_in[14];
    const float* wv        = (const float*)d_in[15];
    const float* bv        = (const float*)d_in[16];
    const float* gamma_pam = (const float*)d_in[17];
    const float* gamma_cam = (const float*)d_in[18];
    const float* w51       = (const float*)d_in[19];
    const float* w52       = (const float*)d_in[24];
    float* out = (float*)d_out;

    float *feat1, *feat2, *q, *k, *v, *energy, *sa_feat, *sc_feat, *sa_conv, *cam_e;
    cudaGetSymbolAddress((void**)&feat1,   g_feat1);
    cudaGetSymbolAddress((void**)&feat2,   g_feat2);
    cudaGetSymbolAddress((void**)&q,       g_q);
    cudaGetSymbolAddress((void**)&k,       g_k);
    cudaGetSymbolAddress((void**)&v,       g_v);
    cudaGetSymbolAddress((void**)&energy,  g_energy);
    cudaGetSymbolAddress((void**)&sa_feat, g_sa_feat);
    cudaGetSymbolAddress((void**)&sc_feat, g_sc_feat);
    cudaGetSymbolAddress((void**)&sa_conv, g_sa_conv);
    cudaGetSymbolAddress((void**)&cam_e,   g_cam_e);

    // 0) fold BN params (sets: 0=bn5a, 1=bn5c, 2=bn51, 3=bn52)
    fold_bn_kernel<<<4, 512>>>(
        (const float*)d_in[2],  (const float*)d_in[3],  (const float*)d_in[4],  (const float*)d_in[5],
        (const float*)d_in[7],  (const float*)d_in[8],  (const float*)d_in[9],  (const float*)d_in[10],
        (const float*)d_in[20], (const float*)d_in[21], (const float*)d_in[22], (const float*)d_in[23],
        (const float*)d_in[25], (const float*)d_in[26], (const float*)d_in[27], (const float*)d_in[28]);

    const dim3 cgrid(8, 64, 2);  // (Cout/64, rows, B)

    // 1) feat1 = CBR(x, w5a)   2) feat2 = CBR(x, w5c)
    conv3x3_bn_relu<<<cgrid, 128>>>(x, w5a, 2048, 0, nullptr, feat1);
    conv3x3_bn_relu<<<cgrid, 128>>>(x, w5c, 2048, 1, nullptr, feat2);

    const long F = 512L * 4096;   // feature batch stride
    const long Q = 64L * 4096;
    const long E = 4096L * 4096;

    // 3) q, k, v (1x1 convs = GEMMs with bias)
    gemm_kernel<0, 1, 1><<<dim3(1, 64, 2), 128>>>(wq, feat1, q, 4096, 512, 512, 4096,
                                                  0, F, Q, bq, nullptr, nullptr, 0);
    gemm_kernel<0, 1, 1><<<dim3(1, 64, 2), 128>>>(wk, feat1, k, 4096, 512, 512, 4096,
                                                  0, F, Q, bk, nullptr, nullptr, 0);
    gemm_kernel<0, 1, 1><<<dim3(8, 64, 2), 128>>>(wv, feat1, v, 4096, 512, 512, 4096,
                                                  0, F, F, bv, nullptr, nullptr, 0);

    // 4) energy[n][m] = sum_c q[c][n] k[c][m]
    gemm_kernel<1, 1, 0><<<dim3(64, 64, 2), 128>>>(q, k, energy, 4096, 64, 4096, 4096,
                                                   Q, Q, E, nullptr, nullptr, nullptr, 0);

    // 5) softmax over m (8192 rows total)
    softmax4096_kernel<<<8192, 256>>>(energy);

    // 6) sa_feat = gamma_pam * (v @ attn^T) + feat1
    gemm_kernel<0, 0, 2><<<dim3(8, 64, 2), 128>>>(v, energy, sa_feat, 4096, 4096, 4096, 4096,
                                                  F, E, F, nullptr, gamma_pam, feat1, F);

    // 7) CAM energy[c][d] = sum_n feat2[c][n] feat2[d][n]
    gemm_kernel<0, 0, 0><<<dim3(8, 8, 2), 128>>>(feat2, feat2, cam_e, 512, 4096, 4096, 4096,
                                                 F, F, 512L * 512, nullptr, nullptr, nullptr, 0);

    // 8) CAM softmax (softmax(rowmax - e) per row, 1024 rows)
    softmax512_cam_kernel<<<1024, 128>>>(cam_e);

    // 9) sc_feat = gamma_cam * (attn @ feat2) + feat2
    gemm_kernel<0, 1, 2><<<dim3(8, 64, 2), 128>>>(cam_e, feat2, sc_feat, 4096, 512, 512, 4096,
                                                  512L * 512, F, F, nullptr, gamma_cam, feat2, F);

    // 10) sa_conv = CBR(sa_feat, w51)
    conv3x3_bn_relu<<<cgrid, 128>>>(sa_feat, w51, 512, 2, nullptr, sa_conv);

    // 11) out = CBR(sc_feat, w52) + sa_conv
    conv3x3_bn_relu<<<cgrid, 128>>>(sc_feat, w52, 512, 3, sa_conv, out);
}

// round 8
// speedup vs baseline: 4.4002x; 4.4002x over previous
#include <cuda_runtime.h>
#include <cstdint>
#include <math.h>

// ===========================================================================
// Scratch (device globals; no allocation in kernel_launch)
// ===========================================================================
__device__ float g_feat1[2 * 512 * 4096];
__device__ float g_feat2[2 * 512 * 4096];
__device__ float g_q[2 * 64 * 4096];
__device__ float g_k[2 * 64 * 4096];
__device__ float g_v[2 * 512 * 4096];
__device__ float g_energy[2 * 4096 * 4096];
__device__ float g_sa_feat[2 * 512 * 4096];
__device__ float g_sc_feat[2 * 512 * 4096];
__device__ float g_sa_conv[2 * 512 * 4096];
__device__ float g_cam_e[2 * 512 * 512];
__device__ float g_scale[4 * 512];
__device__ float g_bias[4 * 512];
__device__ float g_xtf[2 * 2048 * 4096];        // tf32-rounded input
// repacked conv weights: [tap][ci][co], tf32-rounded
__device__ float g_wta[9 * 2048 * 512];
__device__ float g_wtc[9 * 2048 * 512];
__device__ float g_wt1[9 * 512 * 512];
__device__ float g_wt2[9 * 512 * 512];
// tf32-rounded 1x1 weights
__device__ float g_wqr[64 * 512];
__device__ float g_wkr[64 * 512];
__device__ float g_wvr[512 * 512];

// ===========================================================================
// Helpers
// ===========================================================================
__device__ __forceinline__ float tf32r(float x) {
    uint32_t u;
    asm("cvt.rna.tf32.f32 %0, %1;" : "=r"(u) : "f"(x));
    return __uint_as_float(u);
}

__device__ __forceinline__ uint32_t smem_u32(const void* p) {
    uint32_t a;
    asm("{ .reg .u64 t; cvta.to.shared.u64 t, %1; cvt.u32.u64 %0, t; }" : "=r"(a) : "l"(p));
    return a;
}

__device__ __forceinline__ void cp16(uint32_t dst, const float* src) {
    asm volatile("cp.async.ca.shared.global [%0], [%1], 16;" :: "r"(dst), "l"(src));
}
__device__ __forceinline__ void cp4z(uint32_t dst, const float* src, int sz) {
    asm volatile("cp.async.ca.shared.global [%0], [%1], 4, %2;" :: "r"(dst), "l"(src), "r"(sz));
}
#define CP_COMMIT() asm volatile("cp.async.commit_group;" ::: "memory")
#define CP_WAIT0()  asm volatile("cp.async.wait_group 0;" ::: "memory")
#define CP_WAIT1()  asm volatile("cp.async.wait_group 1;" ::: "memory")

#define MMA_TF32(c, a, b0_, b1_) \
    asm volatile("mma.sync.aligned.m16n8k8.row.col.f32.tf32.tf32.f32 " \
        "{%0,%1,%2,%3}, {%4,%5,%6,%7}, {%8,%9}, {%0,%1,%2,%3};" \
        : "+f"((c)[0]), "+f"((c)[1]), "+f"((c)[2]), "+f"((c)[3]) \
        : "r"((a)[0]), "r"((a)[1]), "r"((a)[2]), "r"((a)[3]), "r"(b0_), "r"(b1_))

// pads: k-major rows [k][128] padded to 136 floats; m/n-major rows [.][32] padded to 40.
#define PKM 136
#define PMK 40

// ===========================================================================
// Prep kernels
// ===========================================================================
__global__ void round_tf32_kernel(const float* __restrict__ in, float* __restrict__ o, int n) {
    int t = (blockIdx.x * 256 + threadIdx.x) * 4;
    if (t + 3 < n) {
        float4 v = *(const float4*)&in[t];
        v.x = tf32r(v.x); v.y = tf32r(v.y); v.z = tf32r(v.z); v.w = tf32r(v.w);
        *(float4*)&o[t] = v;
    } else {
        for (int i = t; i < n; i++) o[i] = tf32r(in[i]);
    }
}

// repack w[co][ci][tap] -> o[tap][ci][co], tf32-rounded. Grid (512/32, Cin/8).
__global__ void repack_w(const float* __restrict__ w, float* __restrict__ o, int Cin) {
    __shared__ float s[32][73];
    const int tid = threadIdx.x;
    const int co0 = blockIdx.x * 32;
    const int ci0 = blockIdx.y * 8;
#pragma unroll
    for (int i = 0; i < 9; i++) {
        int e = i * 256 + tid;
        int co = e / 72, r = e % 72;
        s[co][r] = tf32r(w[((size_t)(co0 + co) * Cin + ci0 + r / 9) * 9 + (r % 9)]);
    }
    __syncthreads();
#pragma unroll
    for (int i = 0; i < 9; i++) {
        int e = i * 256 + tid;
        int co = e & 31, f = e >> 5;     // f = 0..71
        int tap = f / 8, ci = f % 8;
        o[((size_t)tap * Cin + ci0 + ci) * 512 + co0 + co] = s[co][ci * 9 + tap];
    }
}

__global__ void fold_bn_kernel(
    const float* s0, const float* b0, const float* m0, const float* v0,
    const float* s1, const float* b1, const float* m1, const float* v1,
    const float* s2, const float* b2, const float* m2, const float* v2,
    const float* s3, const float* b3, const float* m3, const float* v3)
{
    const float* S[4] = {s0, s1, s2, s3};
    const float* B[4] = {b0, b1, b2, b3};
    const float* M[4] = {m0, m1, m2, m3};
    const float* V[4] = {v0, v1, v2, v3};
    int set = blockIdx.x;
    int c = threadIdx.x;
    float inv = rsqrtf(V[set][c] + 1e-5f) * S[set][c];
    g_scale[set * 512 + c] = inv;
    g_bias[set * 512 + c]  = B[set][c] - M[set][c] * inv;
}

// ===========================================================================
// MMA compute core: block tile 128m x 128n, KB=32. 8 warps = 4m x 2n.
// Warp tile 32m x 64n -> 2 m-frags x 8 n-frags of m16n8k8.
// AMK: A smem layout [m][k] (pad 40) else [k][m] (pad 136). BNK analogous.
// ===========================================================================
template <int AMK, int BNK>
__device__ __forceinline__ void mma_block(
    const float* __restrict__ As, const float* __restrict__ Bs,
    int wm, int wn, int group, int tig, float acc[2][8][4])
{
#pragma unroll
    for (int s = 0; s < 4; s++) {
        const int k8 = s * 8;
        uint32_t a[2][4];
#pragma unroll
        for (int fm = 0; fm < 2; fm++) {
            const int m0 = wm + fm * 16 + group;
            if (AMK) {
                const float* p = As + m0 * PMK + k8 + tig;
                a[fm][0] = __float_as_uint(p[0]);
                a[fm][1] = __float_as_uint(p[8 * PMK]);
                a[fm][2] = __float_as_uint(p[4]);
                a[fm][3] = __float_as_uint(p[8 * PMK + 4]);
            } else {
                const float* p = As + (k8 + tig) * PKM + m0;
                a[fm][0] = __float_as_uint(p[0]);
                a[fm][1] = __float_as_uint(p[8]);
                a[fm][2] = __float_as_uint(p[4 * PKM]);
                a[fm][3] = __float_as_uint(p[4 * PKM + 8]);
            }
        }
#pragma unroll
        for (int fn = 0; fn < 8; fn++) {
            const int n0 = wn + fn * 8 + group;
            uint32_t b0, b1;
            if (BNK) {
                const float* p = Bs + n0 * PMK + k8 + tig;
                b0 = __float_as_uint(p[0]);
                b1 = __float_as_uint(p[4]);
            } else {
                const float* p = Bs + (k8 + tig) * PKM + n0;
                b0 = __float_as_uint(p[0]);
                b1 = __float_as_uint(p[4 * PKM]);
            }
            MMA_TF32(acc[0][fn], a[0], b0, b1);
            MMA_TF32(acc[1][fn], a[1], b0, b1);
        }
    }
}

// ===========================================================================
// Implicit-GEMM 3x3 conv + BN + ReLU (+addend) (+tf32 round).
// Tile 128co x 128px (2 rows). Grid (4, 32, B). wT layout [tap][ci][co].
// ===========================================================================
__global__ __launch_bounds__(256, 2) void mma_conv(
    const float* __restrict__ x, const float* __restrict__ wT,
    int Cin, int bnset, const float* __restrict__ addend,
    float* __restrict__ out, int rnd)
{
    extern __shared__ float smf[];
    // layout: A0[32*136] A1 B0[32*136] B1
    const uint32_t sbase = smem_u32(smf);
    float* Abuf[2] = {smf, smf + 32 * PKM};
    float* Bbuf[2] = {smf + 2 * 32 * PKM, smf + 3 * 32 * PKM};
    const uint32_t sbA[2] = {sbase, sbase + 32 * PKM * 4};
    const uint32_t sbB[2] = {sbase + 2 * 32 * PKM * 4, sbase + 3 * 32 * PKM * 4};

    const int tid = threadIdx.x;
    const int warp = tid >> 5, lane = tid & 31;
    const int group = lane >> 2, tig = lane & 3;
    const int wm = (warp & 3) * 32, wn = (warp >> 2) * 64;
    const int coBase = blockIdx.x * 128;
    const int pixBase = blockIdx.y * 128;
    const int y0 = blockIdx.y * 2;
    const int bb = blockIdx.z;

    const float* xb = x + (size_t)bb * Cin * 4096;
    const int NKB = (Cin >> 5) * 9;

    // per-thread constant pieces of B staging
    const int nl = tid & 127;            // pixel within tile
    const int rb0 = tid >> 7;            // 0/1
    const int yy = nl >> 6, xx = nl & 63;
    // A staging constants
    const int cgA = tid & 31;
    const int ra0 = tid >> 5;            // 0..7

    float acc[2][8][4];
#pragma unroll
    for (int i = 0; i < 2; i++)
#pragma unroll
        for (int j = 0; j < 8; j++)
#pragma unroll
            for (int c = 0; c < 4; c++) acc[i][j][c] = 0.f;

    auto stage = [&](int buf, int kb) {
        const int cib = kb / 9;
        const int tap = kb - cib * 9;
        const int ci0 = cib << 5;
        const int dy = tap / 3 - 1;
        const int dx = tap - (tap / 3) * 3 - 1;
        // A: [k=ci][m=co] from wT[tap][ci][co] (contiguous in co)
        const float* wrow = wT + ((size_t)tap * Cin + ci0) * 512 + coBase;
#pragma unroll
        for (int i = 0; i < 4; i++) {
            const int row = ra0 + i * 8;
            cp16(sbA[buf] + (uint32_t)(row * PKM + cgA * 4) * 4, wrow + (size_t)row * 512 + cgA * 4);
        }
        // B: [k=ci][n=px] im2col, scalar zfill
        const int ys = y0 + yy + dy;
        const int xs = xx + dx;
        const int ok = ((unsigned)ys < 64u && (unsigned)xs < 64u) ? 4 : 0;
        const int soff = ok ? ((ys << 6) + xs) : 0;
        const float* bsrc = xb + ((size_t)ci0 << 12) + soff;
#pragma unroll
        for (int i = 0; i < 16; i++) {
            const int row = rb0 + i * 2;
            cp4z(sbB[buf] + (uint32_t)(row * PKM + nl) * 4, bsrc + ((size_t)row << 12), ok);
        }
    };

    stage(0, 0);
    CP_COMMIT();
    for (int kb = 0; kb < NKB; kb++) {
        if (kb + 1 < NKB) {
            stage((kb + 1) & 1, kb + 1);
            CP_COMMIT();
            CP_WAIT1();
        } else {
            CP_WAIT0();
        }
        __syncthreads();
        mma_block<0, 0>(Abuf[kb & 1], Bbuf[kb & 1], wm, wn, group, tig, acc);
        __syncthreads();
    }

    // epilogue: BN + ReLU (+addend) (+round)
#pragma unroll
    for (int fm = 0; fm < 2; fm++) {
#pragma unroll
        for (int half = 0; half < 2; half++) {
            const int co = coBase + wm + fm * 16 + group + half * 8;
            const float sc = g_scale[bnset * 512 + co];
            const float bi = g_bias[bnset * 512 + co];
            float* orow = out + (((size_t)(bb * 512 + co)) << 12) + pixBase;
            const float* arow = addend ? addend + (((size_t)(bb * 512 + co)) << 12) + pixBase : nullptr;
#pragma unroll
            for (int fn = 0; fn < 8; fn++) {
                const int n = wn + fn * 8 + tig * 2;
                float v0 = fmaxf(acc[fm][fn][half * 2 + 0] * sc + bi, 0.f);
                float v1 = fmaxf(acc[fm][fn][half * 2 + 1] * sc + bi, 0.f);
                if (rnd) { v0 = tf32r(v0); v1 = tf32r(v1); }
                if (arow) { v0 += arow[n]; v1 += arow[n + 1]; }
                float2 st = {v0, v1};
                *(float2*)&orow[n] = st;
            }
        }
    }
}

// ===========================================================================
// GEMM: D[m][n] = sum_k a(m,k) b(n,k).  Tile 128x128, KB=32.
//   AMK=1: A[m][k] global row-major (stage [m][k] pad40); AMK=0: A[k][m] (stage [k][m] pad136)
//   BNK=1: B[n][k]; BNK=0: B[k][n]
//   EP: 0 none | 1 +bias[m] | 2 gamma*acc+add | 3 qk split (A rows<64: wq->C, else wk->C2)
//   RND: round output to tf32
// ===========================================================================
template <int AMK, int BNK, int EP, int RND>
__global__ __launch_bounds__(256, 2) void mma_gemm(
    const float* __restrict__ A, const float* __restrict__ Bm, float* __restrict__ C,
    int lda, int ldb, int ldc, int K,
    long sA, long sB, long sC,
    const float* __restrict__ A2, const float* __restrict__ bias, const float* __restrict__ bias2,
    const float* __restrict__ gamma, const float* __restrict__ add, long sAdd,
    float* __restrict__ C2, long sC2)
{
    extern __shared__ float smf[];
    constexpr int ASf = AMK ? 128 * PMK : 32 * PKM;
    constexpr int BSf = BNK ? 128 * PMK : 32 * PKM;
    const uint32_t sbase = smem_u32(smf);
    float* Abuf[2] = {smf, smf + ASf};
    float* Bbuf[2] = {smf + 2 * ASf, smf + 2 * ASf + BSf};
    const uint32_t sbA[2] = {sbase, sbase + ASf * 4};
    const uint32_t sbB[2] = {sbase + 2 * ASf * 4, sbase + (2 * ASf + BSf) * 4};

    const int tid = threadIdx.x;
    const int warp = tid >> 5, lane = tid & 31;
    const int group = lane >> 2, tig = lane & 3;
    const int wm = (warp & 3) * 32, wn = (warp >> 2) * 64;
    const int mBase = blockIdx.x * 128;
    const int nBase = blockIdx.y * 128;
    const int bb = blockIdx.z;

    const float* Ag = A + (size_t)bb * sA;
    const float* Bg = Bm + (size_t)bb * sB;
    const int NKB = K >> 5;

    float acc[2][8][4];
#pragma unroll
    for (int i = 0; i < 2; i++)
#pragma unroll
        for (int j = 0; j < 8; j++)
#pragma unroll
            for (int c = 0; c < 4; c++) acc[i][j][c] = 0.f;

    auto stage = [&](int buf, int kb) {
        const int k0 = kb << 5;
        if (AMK) {
            const int row = tid >> 3, cg = tid & 7;   // 4 iters: rows +32
#pragma unroll
            for (int i = 0; i < 4; i++) {
                const int r = row + i * 32;
                const float* src;
                if (EP == 3)
                    src = (r < 64 ? A + (size_t)r * lda : A2 + (size_t)(r - 64) * lda) + k0 + cg * 4;
                else
                    src = Ag + (size_t)(mBase + r) * lda + k0 + cg * 4;
                cp16(sbA[buf] + (uint32_t)(r * PMK + cg * 4) * 4, src);
            }
        } else {
            const int row = tid >> 5, cg = tid & 31;  // 4 iters: rows +8
#pragma unroll
            for (int i = 0; i < 4; i++) {
                const int r = row + i * 8;
                cp16(sbA[buf] + (uint32_t)(r * PKM + cg * 4) * 4,
                     Ag + (size_t)(k0 + r) * lda + mBase + cg * 4);
            }
        }
        if (BNK) {
            const int row = tid >> 3, cg = tid & 7;
#pragma unroll
            for (int i = 0; i < 4; i++) {
                const int r = row + i * 32;
                cp16(sbB[buf] + (uint32_t)(r * PMK + cg * 4) * 4,
                     Bg + (size_t)(nBase + r) * ldb + k0 + cg * 4);
            }
        } else {
            const int row = tid >> 5, cg = tid & 31;
#pragma unroll
            for (int i = 0; i < 4; i++) {
                const int r = row + i * 8;
                cp16(sbB[buf] + (uint32_t)(r * PKM + cg * 4) * 4,
                     Bg + (size_t)(k0 + r) * ldb + nBase + cg * 4);
            }
        }
    };

    stage(0, 0);
    CP_COMMIT();
    for (int kb = 0; kb < NKB; kb++) {
        if (kb + 1 < NKB) {
            stage((kb + 1) & 1, kb + 1);
            CP_COMMIT();
            CP_WAIT1();
        } else {
            CP_WAIT0();
        }
        __syncthreads();
        mma_block<AMK, BNK>(Abuf[kb & 1], Bbuf[kb & 1], wm, wn, group, tig, acc);
        __syncthreads();
    }

    // epilogue
    const float gv = (EP == 2) ? __ldg(&gamma[0]) : 0.f;
#pragma unroll
    for (int fm = 0; fm < 2; fm++) {
#pragma unroll
        for (int half = 0; half < 2; half++) {
            const int m = mBase + wm + fm * 16 + group + half * 8;
            float bv = 0.f;
            float* dst;
            if (EP == 3) {
                bv = (m < 64) ? __ldg(&bias[m]) : __ldg(&bias2[m - 64]);
                dst = (m < 64) ? C + (size_t)bb * sC + (size_t)m * ldc
                               : C2 + (size_t)bb * sC2 + (size_t)(m - 64) * ldc;
            } else {
                if (EP == 1) bv = __ldg(&bias[m]);
                dst = C + (size_t)bb * sC + (size_t)m * ldc;
            }
            const float* ap = (EP == 2) ? add + (size_t)bb * sAdd + (size_t)m * ldc : nullptr;
#pragma unroll
            for (int fn = 0; fn < 8; fn++) {
                const int n = nBase + wn + fn * 8 + tig * 2;
                float v0 = acc[fm][fn][half * 2 + 0];
                float v1 = acc[fm][fn][half * 2 + 1];
                if (EP == 1 || EP == 3) { v0 += bv; v1 += bv; }
                if (EP == 2) {
                    const float2 a2v = *(const float2*)&ap[n];
                    v0 = gv * v0 + a2v.x;
                    v1 = gv * v1 + a2v.y;
                }
                if (RND) { v0 = tf32r(v0); v1 = tf32r(v1); }
                float2 st = {v0, v1};
                *(float2*)&dst[n] = st;
            }
        }
    }
}

// ===========================================================================
// Softmaxes (attn outputs rounded to tf32 — they feed GEMMs)
// ===========================================================================
__global__ void softmax4096_kernel(float* __restrict__ e)
{
    float* p = e + (size_t)blockIdx.x * 4096;
    const int tid = threadIdx.x;
    float4 v[4];
    float mx = -1e30f;
#pragma unroll
    for (int i = 0; i < 4; i++) {
        v[i] = *(const float4*)&p[i * 1024 + tid * 4];
        mx = fmaxf(mx, fmaxf(fmaxf(v[i].x, v[i].y), fmaxf(v[i].z, v[i].w)));
    }
    __shared__ float red[8];
#pragma unroll
    for (int off = 16; off; off >>= 1) mx = fmaxf(mx, __shfl_xor_sync(0xffffffffu, mx, off));
    if ((tid & 31) == 0) red[tid >> 5] = mx;
    __syncthreads();
    mx = red[0];
#pragma unroll
    for (int i = 1; i < 8; i++) mx = fmaxf(mx, red[i]);
    __syncthreads();
    float s = 0.f;
#pragma unroll
    for (int i = 0; i < 4; i++) {
        v[i].x = __expf(v[i].x - mx); v[i].y = __expf(v[i].y - mx);
        v[i].z = __expf(v[i].z - mx); v[i].w = __expf(v[i].w - mx);
        s += v[i].x + v[i].y + v[i].z + v[i].w;
    }
#pragma unroll
    for (int off = 16; off; off >>= 1) s += __shfl_xor_sync(0xffffffffu, s, off);
    if ((tid & 31) == 0) red[tid >> 5] = s;
    __syncthreads();
    s = 0.f;
#pragma unroll
    for (int i = 0; i < 8; i++) s += red[i];
    const float inv = 1.f / s;
#pragma unroll
    for (int i = 0; i < 4; i++) {
        v[i].x = tf32r(v[i].x * inv); v[i].y = tf32r(v[i].y * inv);
        v[i].z = tf32r(v[i].z * inv); v[i].w = tf32r(v[i].w * inv);
        *(float4*)&p[i * 1024 + tid * 4] = v[i];
    }
}

__global__ void softmax512_cam_kernel(float* __restrict__ e)
{
    float* p = e + (size_t)blockIdx.x * 512;
    const int tid = threadIdx.x;
    float4 v = *(const float4*)&p[tid * 4];
    float mn = fminf(fminf(v.x, v.y), fminf(v.z, v.w));
    __shared__ float red[4];
#pragma unroll
    for (int off = 16; off; off >>= 1) mn = fminf(mn, __shfl_xor_sync(0xffffffffu, mn, off));
    if ((tid & 31) == 0) red[tid >> 5] = mn;
    __syncthreads();
    mn = fminf(fminf(red[0], red[1]), fminf(red[2], red[3]));
    __syncthreads();
    v.x = __expf(mn - v.x); v.y = __expf(mn - v.y);
    v.z = __expf(mn - v.z); v.w = __expf(mn - v.w);
    float s = v.x + v.y + v.z + v.w;
#pragma unroll
    for (int off = 16; off; off >>= 1) s += __shfl_xor_sync(0xffffffffu, s, off);
    if ((tid & 31) == 0) red[tid >> 5] = s;
    __syncthreads();
    s = red[0] + red[1] + red[2] + red[3];
    const float inv = 1.f / s;
    v.x = tf32r(v.x * inv); v.y = tf32r(v.y * inv);
    v.z = tf32r(v.z * inv); v.w = tf32r(v.w * inv);
    *(float4*)&p[tid * 4] = v;
}

// ===========================================================================
// Launch
// ===========================================================================
#define SM_CONV ((4 * 32 * PKM) * 4)
static inline int smem_gemm(int amk, int bnk) {
    int a = amk ? 128 * PMK : 32 * PKM;
    int b = bnk ? 128 * PMK : 32 * PKM;
    return (2 * a + 2 * b) * 4;
}

extern "C" void kernel_launch(void* const* d_in, const int* in_sizes, int n_in,
                              void* d_out, int out_size)
{
    (void)in_sizes; (void)n_in; (void)out_size;

    const float* x         = (const float*)d_in[0];
    const float* w5a       = (const float*)d_in[1];
    const float* w5c       = (const float*)d_in[6];
    const float* wq        = (const float*)d_in[11];
    const float* bq        = (const float*)d_in[12];
    const float* wk        = (const float*)d_in[13];
    const float* bk        = (const float*)d_in[14];
    const float* wv        = (const float*)d_in[15];
    const float* bv        = (const float*)d_in[16];
    const float* gamma_pam = (const float*)d_in[17];
    const float* gamma_cam = (const float*)d_in[18];
    const float* w51       = (const float*)d_in[19];
    const float* w52       = (const float*)d_in[24];
    float* out = (float*)d_out;

    float *feat1, *feat2, *q, *k, *v, *energy, *sa_feat, *sc_feat, *sa_conv, *cam_e;
    float *xtf, *wta, *wtc, *wt1, *wt2, *wqr, *wkr, *wvr;
    cudaGetSymbolAddress((void**)&feat1,   g_feat1);
    cudaGetSymbolAddress((void**)&feat2,   g_feat2);
    cudaGetSymbolAddress((void**)&q,       g_q);
    cudaGetSymbolAddress((void**)&k,       g_k);
    cudaGetSymbolAddress((void**)&v,       g_v);
    cudaGetSymbolAddress((void**)&energy,  g_energy);
    cudaGetSymbolAddress((void**)&sa_feat, g_sa_feat);
    cudaGetSymbolAddress((void**)&sc_feat, g_sc_feat);
    cudaGetSymbolAddress((void**)&sa_conv, g_sa_conv);
    cudaGetSymbolAddress((void**)&cam_e,   g_cam_e);
    cudaGetSymbolAddress((void**)&xtf,     g_xtf);
    cudaGetSymbolAddress((void**)&wta,     g_wta);
    cudaGetSymbolAddress((void**)&wtc,     g_wtc);
    cudaGetSymbolAddress((void**)&wt1,     g_wt1);
    cudaGetSymbolAddress((void**)&wt2,     g_wt2);
    cudaGetSymbolAddress((void**)&wqr,     g_wqr);
    cudaGetSymbolAddress((void**)&wkr,     g_wkr);
    cudaGetSymbolAddress((void**)&wvr,     g_wvr);

    // smem opt-in
    cudaFuncSetAttribute(mma_conv, cudaFuncAttributeMaxDynamicSharedMemorySize, SM_CONV);
    cudaFuncSetAttribute(mma_gemm<1,0,3,1>, cudaFuncAttributeMaxDynamicSharedMemorySize, smem_gemm(1,0));
    cudaFuncSetAttribute(mma_gemm<1,0,1,1>, cudaFuncAttributeMaxDynamicSharedMemorySize, smem_gemm(1,0));
    cudaFuncSetAttribute(mma_gemm<0,0,0,0>, cudaFuncAttributeMaxDynamicSharedMemorySize, smem_gemm(0,0));
    cudaFuncSetAttribute(mma_gemm<1,1,2,1>, cudaFuncAttributeMaxDynamicSharedMemorySize, smem_gemm(1,1));
    cudaFuncSetAttribute(mma_gemm<1,1,0,0>, cudaFuncAttributeMaxDynamicSharedMemorySize, smem_gemm(1,1));
    cudaFuncSetAttribute(mma_gemm<1,0,2,1>, cudaFuncAttributeMaxDynamicSharedMemorySize, smem_gemm(1,0));

    // 0) prep: round x + weights to tf32, repack conv weights, fold BN
    round_tf32_kernel<<<16384, 256>>>(x, xtf, 2 * 2048 * 4096);
    round_tf32_kernel<<<32, 256>>>(wq, wqr, 64 * 512);
    round_tf32_kernel<<<32, 256>>>(wk, wkr, 64 * 512);
    round_tf32_kernel<<<256, 256>>>(wv, wvr, 512 * 512);
    repack_w<<<dim3(16, 256), 256>>>(w5a, wta, 2048);
    repack_w<<<dim3(16, 256), 256>>>(w5c, wtc, 2048);
    repack_w<<<dim3(16, 64), 256>>>(w51, wt1, 512);
    repack_w<<<dim3(16, 64), 256>>>(w52, wt2, 512);
    fold_bn_kernel<<<4, 512>>>(
        (const float*)d_in[2],  (const float*)d_in[3],  (const float*)d_in[4],  (const float*)d_in[5],
        (const float*)d_in[7],  (const float*)d_in[8],  (const float*)d_in[9],  (const float*)d_in[10],
        (const float*)d_in[20], (const float*)d_in[21], (const float*)d_in[22], (const float*)d_in[23],
        (const float*)d_in[25], (const float*)d_in[26], (const float*)d_in[27], (const float*)d_in[28]);

    const dim3 cgrid(4, 32, 2);
    const long F = 512L * 4096;
    const long Q = 64L * 4096;
    const long E = 4096L * 4096;

    // 1) feat1 = CBR(x, w5a); feat2 = CBR(x, w5c)   (rounded for downstream GEMMs)
    mma_conv<<<cgrid, 256, SM_CONV>>>(xtf, wta, 2048, 0, nullptr, feat1, 1);
    mma_conv<<<cgrid, 256, SM_CONV>>>(xtf, wtc, 2048, 1, nullptr, feat2, 1);

    // 2) q,k stacked (M=128: rows<64 -> q, else k).  A=wq/wk [m][k], B=feat1 [k][n]
    mma_gemm<1,0,3,1><<<dim3(1, 32, 2), 256, smem_gemm(1,0)>>>(
        wqr, feat1, q, 512, 4096, 4096, 512, 0, F, Q,
        wkr, bq, bk, nullptr, nullptr, 0, k, Q);

    // 3) v = wv @ feat1 + bv
    mma_gemm<1,0,1,1><<<dim3(4, 32, 2), 256, smem_gemm(1,0)>>>(
        wvr, feat1, v, 512, 4096, 4096, 512, 0, F, F,
        nullptr, bv, nullptr, nullptr, nullptr, 0, nullptr, 0);

    // 4) energy[qpix][kpix] = sum_c q[c][qpix] k[c][kpix].  A KM, B KN, K=64
    mma_gemm<0,0,0,0><<<dim3(32, 32, 2), 256, smem_gemm(0,0)>>>(
        q, k, energy, 4096, 4096, 4096, 64, Q, Q, E,
        nullptr, nullptr, nullptr, nullptr, nullptr, 0, nullptr, 0);

    // 5) PAM softmax (rounds attn)
    softmax4096_kernel<<<8192, 256>>>(energy);

    // 6) sa_feat = gamma_pam * (v @ attn^T) + feat1.  A=v [m][k] MK, B=attn [n][k] NK
    mma_gemm<1,1,2,1><<<dim3(4, 32, 2), 256, smem_gemm(1,1)>>>(
        v, energy, sa_feat, 4096, 4096, 4096, 4096, F, E, F,
        nullptr, nullptr, nullptr, gamma_pam, feat1, F, nullptr, 0);

    // 7) CAM energy = feat2 @ feat2^T.  A MK, B NK, K=4096
    mma_gemm<1,1,0,0><<<dim3(4, 4, 2), 256, smem_gemm(1,1)>>>(
        feat2, feat2, cam_e, 4096, 4096, 512, 4096, F, F, 512L * 512,
        nullptr, nullptr, nullptr, nullptr, nullptr, 0, nullptr, 0);

    // 8) CAM softmax (rounds attn)
    softmax512_cam_kernel<<<1024, 128>>>(cam_e);

    // 9) sc_feat = gamma_cam * (attn @ feat2) + feat2.  A=attn [m][k] MK, B=feat2 [k][n] KN
    mma_gemm<1,0,2,1><<<dim3(4, 32, 2), 256, smem_gemm(1,0)>>>(
        cam_e, feat2, sc_feat, 512, 4096, 4096, 512, 512L * 512, F, F,
        nullptr, nullptr, nullptr, gamma_cam, feat2, F, nullptr, 0);

    // 10) sa_conv = CBR(sa_feat, w51);  out = CBR(sc_feat, w52) + sa_conv
    mma_conv<<<cgrid, 256, SM_CONV>>>(sa_feat, wt1, 512, 2, nullptr, sa_conv, 0);
    mma_conv<<<cgrid, 256, SM_CONV>>>(sc_feat, wt2, 512, 3, sa_conv, out, 0);
}